// round 4
// baseline (speedup 1.0000x reference)
#include <cuda_runtime.h>
#include <cstdint>

#define BB 16
#define NPTS 2048
#define MM 16
#define SS 128
#define NSPLIT 4
#define NCHUNK (NPTS / NSPLIT)        // 512 n per CTA
#define TX 64                          // threads in n direction
#define TY 4                           // threads in s direction
#define NCNT (NCHUNK / TX)             // 8 n per thread
#define NPAIR (NCNT / 2)               // 4 packed pairs
#define SCNT (SS / TY)                 // 32 s per thread
#define K2_SORT_BLOCKS ((BB * NPTS) / 256)   // 128
#define K2_CM_BLOCKS ((BB * MM) / 8)         // 32

static __device__ float4 g_pclT[BB * MM * NPTS];           // [b][m][n] = (-2x,-2y,-2z,|x|^2)
static __device__ float g_d1T[BB * MM * NPTS];             // [b][m][n] min-over-s
static __device__ float g_partmin[BB * MM * NSPLIT * SS];  // per (bm,chunk), per-s min-over-chunk
static __device__ float g_colmean[BB * MM];                // mean_s min_n (clamped)
static __device__ float g_part1[K2_SORT_BLOCKS];           // pcl_to_prim partials

// ---- packed f32x2 helpers ----
#define ADD2(d, a, b)    asm("add.rn.f32x2 %0, %1, %2;" : "=l"(d) : "l"(a), "l"(b))
#define FMA2(d, a, b, c) asm("fma.rn.f32x2 %0, %1, %2, %3;" : "=l"(d) : "l"(a), "l"(b), "l"(c))
#define PACK2(d, lo, hi) asm("mov.b64 %0, {%1, %2};" : "=l"(d) \
                             : "r"(__float_as_uint(lo)), "r"(__float_as_uint(hi)))
#define UNPACK2(lo, hi, s) do { unsigned _ul, _uh;                                  \
    asm("mov.b64 {%0, %1}, %2;" : "=r"(_ul), "=r"(_uh) : "l"(s));                   \
    (lo) = __uint_as_float(_ul); (hi) = __uint_as_float(_uh); } while (0)

// ---------------------------------------------------------------------------
// Kernel 0: smem-tiled transpose. pcl (B,N,M,3) -> pclT[b][m][n] float4
// (-2x,-2y,-2z,|x|^2). Coalesced reads AND writes (the strided side goes
// through padded smem). Grid = B * (N/128) = 256 blocks.
// ---------------------------------------------------------------------------
__global__ __launch_bounds__(256) void k0(const float* __restrict__ pcl) {
    const int blk = blockIdx.x;
    const int b = blk >> 4;
    const int n0 = (blk & 15) * 128;
    const int tid = threadIdx.x;

    __shared__ float sm[128 * 49];   // 128 n-rows of 48 floats, padded to 49

    const float* src = pcl + ((size_t)b * NPTS + n0) * (MM * 3);
#pragma unroll
    for (int k = 0; k < 24; k++) {
        int j = tid + k * 256;               // 0..6143, coalesced
        sm[(j / 48) * 49 + (j % 48)] = src[j];
    }
    __syncthreads();

    const int m = tid >> 4;
    const int l = tid & 15;
#pragma unroll
    for (int r = 0; r < 8; r++) {
        int nl = r * 16 + l;
        const float* row = sm + nl * 49 + m * 3;
        float X = row[0], Y = row[1], Z = row[2];
        g_pclT[(size_t)(b * MM + m) * NPTS + n0 + nl] =
            make_float4(-2.0f * X, -2.0f * Y, -2.0f * Z, X * X + Y * Y + Z * Z);
    }
}

// ---------------------------------------------------------------------------
// Kernel 1: one CTA per (b, m, n-chunk). 2D register tiling; coalesced
// float4 prologue from pclT; hot loop is pure register math (packed f32x2);
// coalesced g_d1T stores.
// ---------------------------------------------------------------------------
__global__ __launch_bounds__(TX * TY) void k1(const float* __restrict__ prim) {
    const int bid = blockIdx.x;            // = bm * NSPLIT + chunk
    const int chunk = bid & (NSPLIT - 1);
    const int bm = bid >> 2;
    const int b = bm >> 4;
    const int m = bm & 15;
    const int tid = threadIdx.x;
    const int x = tid & (TX - 1);
    const int y = tid >> 6;                // 0..3
    const int lane = tid & 31;
    const int warp = tid >> 5;             // = 2*y + (x>=32)

    __shared__ ulonglong2 sAC[SS];         // {(a,a),(c,c)}
    __shared__ ulonglong2 sDQ[SS];         // {(d,d),(q,q)}
    __shared__ float sred[TY * NCHUNK];    // 8KB dmin combine
    __shared__ float sbuf[8][32];          // per-warp smin results

    const float* pp = prim + (size_t)(b * MM + m) * SS * 3;
    for (int s = tid; s < SS; s += TX * TY) {
        float a = pp[3 * s + 0];
        float c = pp[3 * s + 1];
        float d = pp[3 * s + 2];
        float q = a * a + c * c + d * d;
        unsigned long long aa, cc, dd, qq;
        PACK2(aa, a, a); PACK2(cc, c, c); PACK2(dd, d, d); PACK2(qq, q, q);
        sAC[s] = make_ulonglong2(aa, cc);
        sDQ[s] = make_ulonglong2(dd, qq);
    }
    __syncthreads();

    // Coalesced prologue: 8 float4 loads (lane = consecutive n).
    const float4* pt = g_pclT + (size_t)bm * NPTS + chunk * NCHUNK;
    unsigned long long nx2[NPAIR], ny2[NPAIR], nz2[NPAIR], uu2[NPAIR];
    float dmin[NCNT];
#pragma unroll
    for (int p = 0; p < NPAIR; p++) {
        float4 v0 = pt[(2 * p) * TX + x];
        float4 v1 = pt[(2 * p + 1) * TX + x];
        PACK2(nx2[p], v0.x, v1.x);
        PACK2(ny2[p], v0.y, v1.y);
        PACK2(nz2[p], v0.z, v1.z);
        PACK2(uu2[p], v0.w, v1.w);
        dmin[2 * p] = 3.4e38f;
        dmin[2 * p + 1] = 3.4e38f;
    }

    float smin[SCNT];

    // ---- hot loop: 32 s x 8 n per thread, all in registers ----
#pragma unroll
    for (int k = 0; k < SCNT; k++) {
        const int s = y * SCNT + k;
        ulonglong2 ac = sAC[s];
        ulonglong2 dq = sDQ[s];
        float sm0 = 3.4e38f, sm1 = 3.4e38f;
#pragma unroll
        for (int p = 0; p < NPAIR; p++) {
            unsigned long long t;
            ADD2(t, dq.y, uu2[p]);             // q + |x|^2
            FMA2(t, ac.x, nx2[p], t);          // -2 a x
            FMA2(t, ac.y, ny2[p], t);
            FMA2(t, dq.x, nz2[p], t);
            float f0, f1;
            UNPACK2(f0, f1, t);
            dmin[2 * p]     = fminf(dmin[2 * p], f0);
            dmin[2 * p + 1] = fminf(dmin[2 * p + 1], f1);
            sm0 = fminf(sm0, f0);
            sm1 = fminf(sm1, f1);
        }
        smin[k] = fminf(sm0, sm1);
    }

    // ---- epilogue 1: smin — warp butterfly (whole warp shares y => same s) ----
#pragma unroll
    for (int k = 0; k < SCNT; k++) {
#pragma unroll
        for (int off = 16; off > 0; off >>= 1)
            smin[k] = fminf(smin[k], __shfl_xor_sync(0xffffffffu, smin[k], off));
    }
    if (lane == 0) {
#pragma unroll
        for (int k = 0; k < SCNT; k++) sbuf[warp][k] = smin[k];
    }

    // ---- epilogue 2: dmin — combine the 4 y-slices via smem ----
#pragma unroll
    for (int j = 0; j < NCNT; j++) sred[y * NCHUNK + j * TX + x] = dmin[j];
    __syncthreads();

    // 512 n / 256 threads = 2 n per thread; coalesced stores.
    float* d1out = g_d1T + (size_t)bm * NPTS + chunk * NCHUNK;
#pragma unroll
    for (int r = 0; r < 2; r++) {
        int nl = r * 256 + tid;
        float v = fminf(fminf(sred[0 * NCHUNK + nl], sred[1 * NCHUNK + nl]),
                        fminf(sred[2 * NCHUNK + nl], sred[3 * NCHUNK + nl]));
        d1out[nl] = v;
    }

    if (tid < SS) {
        int yy = tid >> 5, kk = tid & 31;
        g_partmin[(size_t)bid * SS + tid] = fminf(sbuf[2 * yy][kk], sbuf[2 * yy + 1][kk]);
    }
}

// ---------------------------------------------------------------------------
// Kernel 2:
//  blocks [0,128): per (b,n) odd-even sort of M=16 (dist,prob) from g_d1T
//  (16 coalesced loads), stick-breaking sum, block-tree partial.
//  blocks [128,160): colmean.
// ---------------------------------------------------------------------------
__global__ __launch_bounds__(256) void k2(const float* __restrict__ probs) {
    if (blockIdx.x < K2_SORT_BLOCKS) {
        const int idx = blockIdx.x * 256 + threadIdx.x;  // < B*N
        const int b = idx >> 11;
        const int n = idx & (NPTS - 1);

        float d[MM], p[MM];
#pragma unroll
        for (int i = 0; i < MM; i++)
            d[i] = g_d1T[(size_t)(b * MM + i) * NPTS + n];
#pragma unroll
        for (int i = 0; i < MM; i++) p[i] = probs[b * MM + i];

#pragma unroll
        for (int r = 0; r < MM; r++) {
#pragma unroll
            for (int i = (r & 1); i + 1 < MM; i += 2) {
                if (d[i] > d[i + 1]) {
                    float td = d[i]; d[i] = d[i + 1]; d[i + 1] = td;
                    float tp = p[i]; p[i] = p[i + 1]; p[i + 1] = tp;
                }
            }
        }

        float run = 1.0f, sum = 0.0f;
#pragma unroll
        for (int i = 0; i < MM; i++) {
            sum += d[i] * p[i] * run;
            run *= (1.0f - p[i]);
        }

        __shared__ float red[256];
        red[threadIdx.x] = sum;
        __syncthreads();
        for (int off = 128; off > 0; off >>= 1) {
            if (threadIdx.x < off) red[threadIdx.x] += red[threadIdx.x + off];
            __syncthreads();
        }
        if (threadIdx.x == 0) g_part1[blockIdx.x] = red[0];
    } else {
        const int bb = blockIdx.x - K2_SORT_BLOCKS;     // 0..31
        const int w = threadIdx.x >> 5;
        const int lane = threadIdx.x & 31;
        const int bm = bb * 8 + w;

        const float* pm = g_partmin + (size_t)bm * NSPLIT * SS;
        float sum = 0.0f;
#pragma unroll
        for (int i = 0; i < SS / 32; i++) {
            int s = lane + 32 * i;
            float mn = fminf(fminf(pm[0 * SS + s], pm[1 * SS + s]),
                             fminf(pm[2 * SS + s], pm[3 * SS + s]));
            if (mn >= 1e30f) mn = 0.0f;   // INF_CLAMP rule
            sum += mn;
        }
#pragma unroll
        for (int off = 16; off > 0; off >>= 1)
            sum += __shfl_down_sync(0xffffffffu, sum, off);
        if (lane == 0) g_colmean[bm] = sum * (1.0f / SS);
    }
}

// ---------------------------------------------------------------------------
// Kernel 3: single block. Areas + normalization + final combine.
// ---------------------------------------------------------------------------
__global__ __launch_bounds__(256) void k3(const float* __restrict__ size_,
                                          const float* __restrict__ probs,
                                          float* __restrict__ out, int out_size) {
    const int tid = threadIdx.x;  // 256 == B*M
    const float FOUR_PI = 12.566370614359172f;

    __shared__ float area[256];
    __shared__ float red[256];
    __shared__ float p1_shared;

    const int b = tid >> 4;

    float s0 = size_[tid * 3 + 0];
    float s1 = size_[tid * 3 + 1];
    float s2 = size_[tid * 3 + 2];
    float inner = (powf(s0 * s1, 1.6f) + powf(s0 * s2, 1.6f) + powf(s1 * s2, 1.6f)) * (1.0f / 3.0f);
    float ar = FOUR_PI * powf(inner, 0.625f);
    area[tid] = ar;
    __syncthreads();

    float sb = 0.0f;
#pragma unroll
    for (int j = 0; j < MM; j++) sb += area[b * MM + j];

    float contrib = g_colmean[tid] * probs[tid] * ((float)MM * ar / sb) * (1.0f / (BB * MM));

    red[tid] = (tid < K2_SORT_BLOCKS) ? g_part1[tid] : 0.0f;
    __syncthreads();
    for (int off = 128; off > 0; off >>= 1) {
        if (tid < off) red[tid] += red[tid + off];
        __syncthreads();
    }
    if (tid == 0) p1_shared = red[0];
    __syncthreads();

    red[tid] = contrib;
    __syncthreads();
    for (int off = 128; off > 0; off >>= 1) {
        if (tid < off) red[tid] += red[tid + off];
        __syncthreads();
    }

    if (tid == 0) {
        float pcl_to_prim = p1_shared * (1.0f / ((float)BB * (float)NPTS));
        float prim_to_pcl = red[0];
        float total = pcl_to_prim + prim_to_pcl;
        if (out_size > 0) out[0] = total;
        if (out_size > 1) out[1] = pcl_to_prim;
        if (out_size > 2) out[2] = prim_to_pcl;
        if (out_size > 3) out[3] = 0.0f;
    }
}

extern "C" void kernel_launch(void* const* d_in, const int* in_sizes, int n_in,
                              void* d_out, int out_size) {
    const float* pcl   = (const float*)d_in[0];  // (B, N, M, 3)
    const float* prim  = (const float*)d_in[1];  // (B, M, S, 3)
    const float* size_ = (const float*)d_in[2];  // (B, M, 3)
    const float* probs = (const float*)d_in[3];  // (B, M)

    k0<<<BB * (NPTS / 128), 256>>>(pcl);
    k1<<<BB * MM * NSPLIT, TX * TY>>>(prim);
    k2<<<K2_SORT_BLOCKS + K2_CM_BLOCKS, 256>>>(probs);
    k3<<<1, 256>>>(size_, probs, (float*)d_out, out_size);
}

// round 5
// speedup vs baseline: 1.0936x; 1.0936x over previous
#include <cuda_runtime.h>
#include <cstdint>

#define BB 16
#define NPTS 2048
#define MM 16
#define SS 128
#define NSPLIT 4
#define NCHUNK (NPTS / NSPLIT)        // 512 n per CTA
#define TX 64                          // threads in n direction
#define TY 4                           // threads in s direction
#define NCNT (NCHUNK / TX)             // 8 n per thread
#define NPAIR (NCNT / 2)               // 4 packed pairs
#define SCNT (SS / TY)                 // 32 s per thread
#define SPAD 257                       // padded row stride (conflict-free epilogue)
#define K2_SORT_BLOCKS ((BB * NPTS) / 256)   // 128
#define K2_CM_BLOCKS ((BB * MM) / 8)         // 32

static __device__ float4 g_pclT[BB * MM * NPTS];           // [b][m][n] = (-2x,-2y,-2z,|x|^2)
static __device__ float g_d1T[BB * MM * NPTS];             // [b][m][n] min-over-s
static __device__ float g_partmin[BB * MM * NSPLIT * SS];  // per (bm,chunk), per-s min-over-chunk
static __device__ float g_colmean[BB * MM];                // mean_s min_n (clamped)
static __device__ float g_part1[K2_SORT_BLOCKS];           // pcl_to_prim partials

// ---- packed f32x2 helpers ----
#define ADD2(d, a, b)    asm("add.rn.f32x2 %0, %1, %2;" : "=l"(d) : "l"(a), "l"(b))
#define FMA2(d, a, b, c) asm("fma.rn.f32x2 %0, %1, %2, %3;" : "=l"(d) : "l"(a), "l"(b), "l"(c))
#define PACK2(d, lo, hi) asm("mov.b64 %0, {%1, %2};" : "=l"(d) \
                             : "r"(__float_as_uint(lo)), "r"(__float_as_uint(hi)))
#define UNPACK2(lo, hi, s) do { unsigned _ul, _uh;                                  \
    asm("mov.b64 {%0, %1}, %2;" : "=r"(_ul), "=r"(_uh) : "l"(s));                   \
    (lo) = __uint_as_float(_ul); (hi) = __uint_as_float(_uh); } while (0)

// ---------------------------------------------------------------------------
// Kernel 0: smem-tiled transpose. pcl (B,N,M,3) -> pclT[b][m][n] float4
// (-2x,-2y,-2z,|x|^2). Coalesced both sides.
// ---------------------------------------------------------------------------
__global__ __launch_bounds__(256) void k0(const float* __restrict__ pcl) {
    const int blk = blockIdx.x;
    const int b = blk >> 4;
    const int n0 = (blk & 15) * 128;
    const int tid = threadIdx.x;

    __shared__ float sm[128 * 49];

    const float* src = pcl + ((size_t)b * NPTS + n0) * (MM * 3);
#pragma unroll
    for (int k = 0; k < 24; k++) {
        int j = tid + k * 256;
        sm[(j / 48) * 49 + (j % 48)] = src[j];
    }
    __syncthreads();

    const int m = tid >> 4;
    const int l = tid & 15;
#pragma unroll
    for (int r = 0; r < 8; r++) {
        int nl = r * 16 + l;
        const float* row = sm + nl * 49 + m * 3;
        float X = row[0], Y = row[1], Z = row[2];
        g_pclT[(size_t)(b * MM + m) * NPTS + n0 + nl] =
            make_float4(-2.0f * X, -2.0f * Y, -2.0f * Z, X * X + Y * Y + Z * Z);
    }
}

// ---------------------------------------------------------------------------
// Kernel 1: one CTA per (b, m, n-chunk). 2D register tiling for the n-axis
// outputs (dmin in regs), smem for the s-axis outputs (one STS per iteration,
// no shuffles, no 32-register accumulator). __launch_bounds__(256,3) keeps
// regs <= 84 so 3 CTAs/SM fit -> 6 warps/SMSP for latency hiding.
// ---------------------------------------------------------------------------
__global__ __launch_bounds__(TX * TY, 3) void k1(const float* __restrict__ prim) {
    const int bid = blockIdx.x;            // = bm * NSPLIT + chunk
    const int chunk = bid & (NSPLIT - 1);
    const int bm = bid >> 2;
    const int b = bm >> 4;
    const int m = bm & 15;
    const int tid = threadIdx.x;
    const int x = tid & (TX - 1);
    const int y = tid >> 6;                // 0..3

    __shared__ ulonglong2 sAC[SS];         // {(a,a),(c,c)}   2KB
    __shared__ ulonglong2 sDQ[SS];         // {(d,d),(q,q)}   2KB
    __shared__ float sminS[SCNT * SPAD];   // [k][tid], padded rows  ~33KB
    __shared__ float sred[TY * NCHUNK];    // dmin combine    8KB

    const float* pp = prim + (size_t)(b * MM + m) * SS * 3;
    for (int s = tid; s < SS; s += TX * TY) {
        float a = pp[3 * s + 0];
        float c = pp[3 * s + 1];
        float d = pp[3 * s + 2];
        float q = a * a + c * c + d * d;
        unsigned long long aa, cc, dd, qq;
        PACK2(aa, a, a); PACK2(cc, c, c); PACK2(dd, d, d); PACK2(qq, q, q);
        sAC[s] = make_ulonglong2(aa, cc);
        sDQ[s] = make_ulonglong2(dd, qq);
    }
    __syncthreads();

    // Coalesced prologue: 8 float4 loads (lane = consecutive n).
    const float4* pt = g_pclT + (size_t)bm * NPTS + chunk * NCHUNK;
    unsigned long long nx2[NPAIR], ny2[NPAIR], nz2[NPAIR], uu2[NPAIR];
    float dmin[NCNT];
#pragma unroll
    for (int p = 0; p < NPAIR; p++) {
        float4 v0 = pt[(2 * p) * TX + x];
        float4 v1 = pt[(2 * p + 1) * TX + x];
        PACK2(nx2[p], v0.x, v1.x);
        PACK2(ny2[p], v0.y, v1.y);
        PACK2(nz2[p], v0.z, v1.z);
        PACK2(uu2[p], v0.w, v1.w);
        dmin[2 * p] = 3.4e38f;
        dmin[2 * p + 1] = 3.4e38f;
    }

    // ---- hot loop: 32 s x 8 n per thread; dmin in regs, smin -> one STS ----
#pragma unroll
    for (int k = 0; k < SCNT; k++) {
        const int s = y * SCNT + k;
        ulonglong2 ac = sAC[s];
        ulonglong2 dq = sDQ[s];
        float pm[NPAIR];
#pragma unroll
        for (int p = 0; p < NPAIR; p++) {
            unsigned long long t;
            ADD2(t, dq.y, uu2[p]);             // q + |x|^2
            FMA2(t, ac.x, nx2[p], t);          // -2 a x
            FMA2(t, ac.y, ny2[p], t);
            FMA2(t, dq.x, nz2[p], t);
            float f0, f1;
            UNPACK2(f0, f1, t);
            dmin[2 * p]     = fminf(dmin[2 * p], f0);
            dmin[2 * p + 1] = fminf(dmin[2 * p + 1], f1);
            pm[p] = fminf(f0, f1);
        }
        sminS[k * SPAD + tid] =
            fminf(fminf(pm[0], pm[1]), fminf(pm[2], pm[3]));
    }

    // ---- epilogue 1: dmin — combine the 4 y-slices via smem ----
#pragma unroll
    for (int j = 0; j < NCNT; j++) sred[y * NCHUNK + j * TX + x] = dmin[j];
    __syncthreads();

    float* d1out = g_d1T + (size_t)bm * NPTS + chunk * NCHUNK;
#pragma unroll
    for (int r = 0; r < 2; r++) {
        int nl = r * 256 + tid;
        float v = fminf(fminf(sred[0 * NCHUNK + nl], sred[1 * NCHUNK + nl]),
                        fminf(sred[2 * NCHUNK + nl], sred[3 * NCHUNK + nl]));
        d1out[nl] = v;
    }

    // ---- epilogue 2: smin — per s, min over its 64 contributing threads ----
    // thread t < 128 handles s = t: row k = t&31, cols [64*(t>>5), +64).
    // bank(addr) = ((t&31) + i) % 32 -> conflict-free for fixed i.
    if (tid < SS) {
        const int kk = tid & 31;
        const int yy = tid >> 5;
        const float* rowp = sminS + kk * SPAD + 64 * yy;
        float v = rowp[0];
#pragma unroll
        for (int i = 1; i < 64; i++) v = fminf(v, rowp[i]);
        g_partmin[(size_t)bid * SS + tid] = v;
    }
}

// ---------------------------------------------------------------------------
// Kernel 2:
//  blocks [0,128): per (b,n) odd-even sort of M=16 (dist,prob) from g_d1T
//  (16 coalesced loads), stick-breaking sum, block-tree partial.
//  blocks [128,160): colmean.
// ---------------------------------------------------------------------------
__global__ __launch_bounds__(256) void k2(const float* __restrict__ probs) {
    if (blockIdx.x < K2_SORT_BLOCKS) {
        const int idx = blockIdx.x * 256 + threadIdx.x;  // < B*N
        const int b = idx >> 11;
        const int n = idx & (NPTS - 1);

        float d[MM], p[MM];
#pragma unroll
        for (int i = 0; i < MM; i++)
            d[i] = g_d1T[(size_t)(b * MM + i) * NPTS + n];
#pragma unroll
        for (int i = 0; i < MM; i++) p[i] = probs[b * MM + i];

#pragma unroll
        for (int r = 0; r < MM; r++) {
#pragma unroll
            for (int i = (r & 1); i + 1 < MM; i += 2) {
                if (d[i] > d[i + 1]) {
                    float td = d[i]; d[i] = d[i + 1]; d[i + 1] = td;
                    float tp = p[i]; p[i] = p[i + 1]; p[i + 1] = tp;
                }
            }
        }

        float run = 1.0f, sum = 0.0f;
#pragma unroll
        for (int i = 0; i < MM; i++) {
            sum += d[i] * p[i] * run;
            run *= (1.0f - p[i]);
        }

        __shared__ float red[256];
        red[threadIdx.x] = sum;
        __syncthreads();
        for (int off = 128; off > 0; off >>= 1) {
            if (threadIdx.x < off) red[threadIdx.x] += red[threadIdx.x + off];
            __syncthreads();
        }
        if (threadIdx.x == 0) g_part1[blockIdx.x] = red[0];
    } else {
        const int bb = blockIdx.x - K2_SORT_BLOCKS;     // 0..31
        const int w = threadIdx.x >> 5;
        const int lane = threadIdx.x & 31;
        const int bm = bb * 8 + w;

        const float* pm = g_partmin + (size_t)bm * NSPLIT * SS;
        float sum = 0.0f;
#pragma unroll
        for (int i = 0; i < SS / 32; i++) {
            int s = lane + 32 * i;
            float mn = fminf(fminf(pm[0 * SS + s], pm[1 * SS + s]),
                             fminf(pm[2 * SS + s], pm[3 * SS + s]));
            if (mn >= 1e30f) mn = 0.0f;   // INF_CLAMP rule
            sum += mn;
        }
#pragma unroll
        for (int off = 16; off > 0; off >>= 1)
            sum += __shfl_down_sync(0xffffffffu, sum, off);
        if (lane == 0) g_colmean[bm] = sum * (1.0f / SS);
    }
}

// ---------------------------------------------------------------------------
// Kernel 3: single block. Areas (fast __powf) + normalization + final combine.
// ---------------------------------------------------------------------------
__global__ __launch_bounds__(256) void k3(const float* __restrict__ size_,
                                          const float* __restrict__ probs,
                                          float* __restrict__ out, int out_size) {
    const int tid = threadIdx.x;  // 256 == B*M
    const float FOUR_PI = 12.566370614359172f;

    __shared__ float area[256];
    __shared__ float red[256];
    __shared__ float p1_shared;

    const int b = tid >> 4;

    float s0 = size_[tid * 3 + 0];
    float s1 = size_[tid * 3 + 1];
    float s2 = size_[tid * 3 + 2];
    // sizes are in [0.05, 1] -> strictly positive; fast MUFU-based pow is safe.
    float inner = (__powf(s0 * s1, 1.6f) + __powf(s0 * s2, 1.6f) + __powf(s1 * s2, 1.6f))
                  * (1.0f / 3.0f);
    float ar = FOUR_PI * __powf(inner, 0.625f);
    area[tid] = ar;
    __syncthreads();

    float sb = 0.0f;
#pragma unroll
    for (int j = 0; j < MM; j++) sb += area[b * MM + j];

    float contrib = g_colmean[tid] * probs[tid] * ((float)MM * ar / sb) * (1.0f / (BB * MM));

    red[tid] = (tid < K2_SORT_BLOCKS) ? g_part1[tid] : 0.0f;
    __syncthreads();
    for (int off = 128; off > 0; off >>= 1) {
        if (tid < off) red[tid] += red[tid + off];
        __syncthreads();
    }
    if (tid == 0) p1_shared = red[0];
    __syncthreads();

    red[tid] = contrib;
    __syncthreads();
    for (int off = 128; off > 0; off >>= 1) {
        if (tid < off) red[tid] += red[tid + off];
        __syncthreads();
    }

    if (tid == 0) {
        float pcl_to_prim = p1_shared * (1.0f / ((float)BB * (float)NPTS));
        float prim_to_pcl = red[0];
        float total = pcl_to_prim + prim_to_pcl;
        if (out_size > 0) out[0] = total;
        if (out_size > 1) out[1] = pcl_to_prim;
        if (out_size > 2) out[2] = prim_to_pcl;
        if (out_size > 3) out[3] = 0.0f;
    }
}

extern "C" void kernel_launch(void* const* d_in, const int* in_sizes, int n_in,
                              void* d_out, int out_size) {
    const float* pcl   = (const float*)d_in[0];  // (B, N, M, 3)
    const float* prim  = (const float*)d_in[1];  // (B, M, S, 3)
    const float* size_ = (const float*)d_in[2];  // (B, M, 3)
    const float* probs = (const float*)d_in[3];  // (B, M)

    k0<<<BB * (NPTS / 128), 256>>>(pcl);
    k1<<<BB * MM * NSPLIT, TX * TY>>>(prim);
    k2<<<K2_SORT_BLOCKS + K2_CM_BLOCKS, 256>>>(probs);
    k3<<<1, 256>>>(size_, probs, (float*)d_out, out_size);
}